// round 15
// baseline (speedup 1.0000x reference)
#include <cuda_runtime.h>
#include <cuda_fp16.h>
#include <cstdint>

#define BSZ    2
#define SEQ    2048
#define DMODEL 1024
#define NHEAD  16
#define DKH    64
#define MROWS  (BSZ * SEQ)   // 4096

// Scratch (allocation-free rule: __device__ globals). All fp16.
__device__ __half g_xh[MROWS * DMODEL];          // x in half
__device__ __half g_wh[4 * DMODEL * DMODEL];     // Wq,Wk,Wv,Wo in half
__device__ __half g_q[MROWS * DMODEL];           // q (scaled)
__device__ __half g_k[MROWS * DMODEL];           // k
__device__ __half g_v[MROWS * DMODEL];           // vt[b][h][64][2048]
__device__ __half g_a[MROWS * DMODEL];           // attention output (half)

// ---------------------------------------------------------------------------
// helpers (sm_80+ features only — the build targets plain sm_103)
// ---------------------------------------------------------------------------
__device__ __forceinline__ void mma_f16(
    float& d0, float& d1, float& d2, float& d3,
    uint32_t a0, uint32_t a1, uint32_t a2, uint32_t a3,
    uint32_t b0, uint32_t b1)
{
    asm volatile(
        "mma.sync.aligned.m16n8k16.row.col.f32.f16.f16.f32 "
        "{%0,%1,%2,%3}, {%4,%5,%6,%7}, {%8,%9}, {%0,%1,%2,%3};"
        : "+f"(d0), "+f"(d1), "+f"(d2), "+f"(d3)
        : "r"(a0), "r"(a1), "r"(a2), "r"(a3), "r"(b0), "r"(b1));
}

__device__ __forceinline__ void ldsm_x4(
    uint32_t& r0, uint32_t& r1, uint32_t& r2, uint32_t& r3, uint32_t addr)
{
    asm volatile("ldmatrix.sync.aligned.m8n8.x4.shared.b16 {%0,%1,%2,%3}, [%4];"
                 : "=r"(r0), "=r"(r1), "=r"(r2), "=r"(r3) : "r"(addr));
}

__device__ __forceinline__ uint32_t smem_u32(const void* p) {
    uint32_t a;
    asm("{ .reg .u64 t; cvta.to.shared.u64 t, %1; cvt.u32.u64 %0, t; }"
        : "=r"(a) : "l"(p));
    return a;
}

__device__ __forceinline__ uint32_t h2u(__half2 h) {
    return *reinterpret_cast<uint32_t*>(&h);
}

// packed half2 exp2 (sm_75+): one MUFU op per pair
__device__ __forceinline__ uint32_t ex2_h2(uint32_t x) {
    uint32_t r;
    asm("ex2.approx.f16x2 %0, %1;" : "=r"(r) : "r"(x));
    return r;
}

__device__ __forceinline__ void cp16(uint32_t dst, const void* src) {
    asm volatile("cp.async.ca.shared.global [%0], [%1], 16;"
                 :: "r"(dst), "l"(src) : "memory");
}
#define CP_COMMIT() asm volatile("cp.async.commit_group;" ::: "memory")
#define CP_WAIT0()  asm volatile("cp.async.wait_group 0;" ::: "memory")

// ---------------------------------------------------------------------------
// Prepass: fp32 -> fp16 conversion (producer-side; enables cp.async loaders)
// ---------------------------------------------------------------------------
__global__ __launch_bounds__(256) void f2h(
    const float* __restrict__ s, __half* __restrict__ d, int n)
{
    const int i = (blockIdx.x * 256 + threadIdx.x) * 8;
    if (i < n) {
        float4 a = *(const float4*)(s + i);
        float4 b = *(const float4*)(s + i + 4);
        union { __half2 h[4]; uint4 u; } u;
        u.h[0] = __floats2half2_rn(a.x, a.y);
        u.h[1] = __floats2half2_rn(a.z, a.w);
        u.h[2] = __floats2half2_rn(b.x, b.y);
        u.h[3] = __floats2half2_rn(b.z, b.w);
        *(uint4*)(d + i) = u.u;
    }
}

__global__ __launch_bounds__(256) void f2h4(
    const float* __restrict__ w0, const float* __restrict__ w1,
    const float* __restrict__ w2, const float* __restrict__ w3,
    __half* __restrict__ d)
{
    const float* srcs[4] = {w0, w1, w2, w3};
    const float* s = srcs[blockIdx.y];
    __half* dd = d + (size_t)blockIdx.y * DMODEL * DMODEL;
    const int i = (blockIdx.x * 256 + threadIdx.x) * 8;
    float4 a = *(const float4*)(s + i);
    float4 b = *(const float4*)(s + i + 4);
    union { __half2 h[4]; uint4 u; } u;
    u.h[0] = __floats2half2_rn(a.x, a.y);
    u.h[1] = __floats2half2_rn(a.z, a.w);
    u.h[2] = __floats2half2_rn(b.x, b.y);
    u.h[3] = __floats2half2_rn(b.z, b.w);
    *(uint4*)(dd + i) = u.u;
}

// ---------------------------------------------------------------------------
// fp16 GEMM NT body (unchanged — validated)
// ---------------------------------------------------------------------------
#define GEMM_SMEM (2 * 32768)   // 65536 B

__device__ __forceinline__ void gemm_body(
    const __half* __restrict__ A, const __half* __restrict__ W,
    void* __restrict__ Cv, float oscale, int mode, char* smg)
{
    const int tid  = threadIdx.x;
    const int lane = tid & 31;
    const int wm   = (tid >> 5) & 3;
    const int wn   = tid >> 7;
    const int m0 = blockIdx.y * 128;
    const int n0 = blockIdx.x * 128;
    const uint32_t smb = smem_u32(smg);

    const int lr  = tid >> 1;
    const int lc4 = (tid & 1) * 4;
    const __half* Ag = A + (size_t)(m0 + lr) * DMODEL + lc4 * 8;
    const __half* Wg = W + (size_t)(n0 + lr) * DMODEL + lc4 * 8;
    const uint32_t sBase = lc4 * 2048 + lr * 16;

    float acc[2][8][4];
#pragma unroll
    for (int i = 0; i < 2; i++)
#pragma unroll
        for (int j = 0; j < 8; j++)
#pragma unroll
            for (int r = 0; r < 4; r++) acc[i][j][r] = 0.0f;

    const int NCH = DMODEL / 64;   // 16

#pragma unroll
    for (int j = 0; j < 4; j++) {
        cp16(smb + sBase + j * 2048,         Ag + j * 8);
        cp16(smb + 16384 + sBase + j * 2048, Wg + j * 8);
    }
    CP_COMMIT();

    for (int s = 0; s < NCH; s++) {
        CP_WAIT0();
        __syncthreads();

        if (s + 1 < NCH) {
            const uint32_t st = smb + ((s + 1) & 1) * 32768;
            const int k0 = (s + 1) * 64;
#pragma unroll
            for (int j = 0; j < 4; j++) {
                cp16(st + sBase + j * 2048,         Ag + k0 + j * 8);
                cp16(st + 16384 + sBase + j * 2048, Wg + k0 + j * 8);
            }
            CP_COMMIT();
        }

        const uint32_t st = smb + (s & 1) * 32768;
#pragma unroll
        for (int ks = 0; ks < 4; ks++) {
            uint32_t af[2][4];
            uint32_t bf[8][2];
#pragma unroll
            for (int mt = 0; mt < 2; mt++) {
                const uint32_t addr = st + (2 * ks + (lane >> 4)) * 2048
                                    + (wm * 32 + mt * 16 + (lane & 15)) * 16;
                ldsm_x4(af[mt][0], af[mt][1], af[mt][2], af[mt][3], addr);
            }
#pragma unroll
            for (int p = 0; p < 4; p++) {
                const uint32_t addr = st + 16384 + (2 * ks + ((lane >> 3) & 1)) * 2048
                                    + (wn * 64 + p * 16 + ((lane >> 4) << 3) + (lane & 7)) * 16;
                ldsm_x4(bf[2 * p][0], bf[2 * p][1], bf[2 * p + 1][0], bf[2 * p + 1][1], addr);
            }
#pragma unroll
            for (int mt = 0; mt < 2; mt++)
#pragma unroll
                for (int nt = 0; nt < 8; nt++)
                    mma_f16(acc[mt][nt][0], acc[mt][nt][1],
                            acc[mt][nt][2], acc[mt][nt][3],
                            af[mt][0], af[mt][1], af[mt][2], af[mt][3],
                            bf[nt][0], bf[nt][1]);
        }
    }

    const int g = lane >> 2, q = lane & 3;
#pragma unroll
    for (int mt = 0; mt < 2; mt++) {
        const int mrow = m0 + wm * 32 + mt * 16 + g;
#pragma unroll
        for (int nt = 0; nt < 8; nt++) {
            const int ncol = n0 + wn * 64 + nt * 8 + 2 * q;
            if (mode == 0) {
                float* C = (float*)Cv;
                *(float2*)(C + (size_t)mrow * DMODEL + ncol) =
                    make_float2(acc[mt][nt][0], acc[mt][nt][1]);
                *(float2*)(C + (size_t)(mrow + 8) * DMODEL + ncol) =
                    make_float2(acc[mt][nt][2], acc[mt][nt][3]);
            } else if (mode == 1) {
                __half2* C = (__half2*)Cv;
                C[((size_t)mrow * DMODEL + ncol) >> 1] =
                    __floats2half2_rn(acc[mt][nt][0] * oscale, acc[mt][nt][1] * oscale);
                C[((size_t)(mrow + 8) * DMODEL + ncol) >> 1] =
                    __floats2half2_rn(acc[mt][nt][2] * oscale, acc[mt][nt][3] * oscale);
            } else {
                // vt[((b*NHEAD + h)*64 + d) * SEQ + s]
                __half* C = (__half*)Cv;
                const int h = ncol >> 6, d = ncol & 63;
                const size_t hb = ((size_t)((mrow >> 11) * NHEAD + h) * 64);
                const int s0 = mrow & 2047;
                C[(hb + d)     * SEQ + s0]     = __float2half_rn(acc[mt][nt][0]);
                C[(hb + d + 1) * SEQ + s0]     = __float2half_rn(acc[mt][nt][1]);
                C[(hb + d)     * SEQ + s0 + 8] = __float2half_rn(acc[mt][nt][2]);
                C[(hb + d + 1) * SEQ + s0 + 8] = __float2half_rn(acc[mt][nt][3]);
            }
        }
    }
}

__global__ __launch_bounds__(256, 2) void gemm_qkv(
    const __half* __restrict__ xh, const __half* __restrict__ wh,
    __half* __restrict__ qb, __half* __restrict__ kb, __half* __restrict__ vb,
    float qscale)
{
    extern __shared__ char smg[];
    const int z = blockIdx.z;
    const __half* W = wh + (size_t)z * DMODEL * DMODEL;
    void* C   = (z == 0) ? (void*)qb : (z == 1) ? (void*)kb : (void*)vb;
    const float sc = (z == 0) ? qscale : 1.0f;
    const int mode = (z == 2) ? 2 : 1;
    gemm_body(xh, W, C, sc, mode, smg);
}

__global__ __launch_bounds__(256, 2) void gemm_out(
    const __half* __restrict__ A, const __half* __restrict__ W,
    float* __restrict__ C)
{
    extern __shared__ char smg[];
    gemm_body(A, W, C, 1.0f, 0, smg);
}

// ---------------------------------------------------------------------------
// fp16 flash attention (causal), warp-pair KV split + PER-WARP online softmax.
// Warp pair (2rg, 2rg+1) shares 32 query rows, splits the 64 KV columns.
// Each warp runs a private online max over its half (P peaks at 1.0: full
// fp16 precision); halves are merged at the end with the standard
// split-softmax max-reconciliation. m initialized to -100 (finite) so a
// fully-masked diagonal sub-tile is a clean no-op.
// ---------------------------------------------------------------------------
#define FH_LD        72
#define FH_LDB       (FH_LD * 2)              // 144 bytes per row
#define FH_PS_HALVES (128 * FH_LD)            // 9216 (Q staging)
#define FH_STG_HALVES (2 * 64 * FH_LD)        // 9216 (K + V)
#define FA_SMEM ((FH_PS_HALVES + 2 * FH_STG_HALVES) * 2)   // 55296 B
#define ONES_H2 0x3C003C00u                   // half2(1.0, 1.0)
#define MINIT   (-100.0f)
#define MASKV   (-1e30f)

__global__ __launch_bounds__(256, 1) void flash_attn_f16(
    const __half* __restrict__ Q, const __half* __restrict__ K,
    const __half* __restrict__ Vt, __half* __restrict__ O)
{
    extern __shared__ __half sh[];

    const int tid  = threadIdx.x;
    const int w    = tid >> 5;
    const int lane = tid & 31;
    const int g    = lane >> 2;
    const int q    = lane & 3;
    const int rg   = w >> 1;          // row group 0..3 (32 rows each)
    const int kvh  = w & 1;           // which KV half this warp owns
    const int co   = kvh * 32;        // kv column offset
    const int qb = gridDim.x - 1 - blockIdx.x;   // reversed: longest first
    const int h  = blockIdx.y, b = blockIdx.z;
    const int q0 = qb * 128;
    const size_t baseh = (size_t)b * SEQ * DMODEL + (size_t)h * DKH;
    const size_t vbase = ((size_t)(b * NHEAD + h)) * 64 * SEQ;

    const uint32_t smb = smem_u32(sh);
    const uint32_t lm_row = ((lane >> 4) << 3) + (lane & 7);
    const uint32_t lm_koff = ((lane >> 3) & 1) * 16;

    const int ntiles = 2 * qb + 2;

    // --- prologue: async-stage Q (128 rows x 128B) and KV tile 0 ---
    for (int i = tid; i < 128 * 8; i += 256) {
        const int r = i >> 3, c = (i & 7) * 8;
        cp16(smb + (r * FH_LD + c) * 2, Q + baseh + (size_t)(q0 + r) * DMODEL + c);
    }
    {
        const int lrk = tid >> 3, lck = (tid & 7) * 8;
        const uint32_t kb0 = smb + FH_PS_HALVES * 2;
        const uint32_t vb0 = kb0 + 64 * FH_LD * 2;
#pragma unroll
        for (int j = 0; j < 2; j++) {
            const int r = lrk + 32 * j;
            cp16(kb0 + (r * FH_LD + lck) * 2, K + baseh + (size_t)r * DMODEL + lck);
            cp16(vb0 + (r * FH_LD + lck) * 2, Vt + vbase + (size_t)r * SEQ + lck);
        }
    }
    CP_COMMIT();
    CP_WAIT0();
    __syncthreads();

    // --- lift Q (rows rg*32 .. +31) into register fragments qf[mt][ks][4] ---
    uint32_t qf[2][4][4];
#pragma unroll
    for (int mt = 0; mt < 2; mt++) {
        const uint32_t* r0p = (const uint32_t*)sh + (rg * 32 + mt * 16 + g) * 36;
        const uint32_t* r1p = r0p + 8 * 36;
#pragma unroll
        for (int ks = 0; ks < 4; ks++) {
            qf[mt][ks][0] = r0p[ks * 8 + q];
            qf[mt][ks][1] = r1p[ks * 8 + q];
            qf[mt][ks][2] = r0p[ks * 8 + q + 4];
            qf[mt][ks][3] = r1p[ks * 8 + q + 4];
        }
    }

    float acc[2][8][4];
    float lacc[2][4];
    float m[2][2];                    // running max: [mt][row-half (g / g+8)]
#pragma unroll
    for (int mt = 0; mt < 2; mt++) {
#pragma unroll
        for (int nt = 0; nt < 8; nt++)
#pragma unroll
            for (int r = 0; r < 4; r++) acc[mt][nt][r] = 0.0f;
#pragma unroll
        for (int r = 0; r < 4; r++) lacc[mt][r] = 0.0f;
        m[mt][0] = MINIT; m[mt][1] = MINIT;
    }

    const int rmin = q0 + rg * 32;    // warp's first query row

    for (int kb = 0; kb < ntiles; kb++) {
        const int kv0 = kb * 64;

        // --- issue cp.async for next tile into the other stage ---
        if (kb + 1 < ntiles) {
            const int lrk = tid >> 3, lck = (tid & 7) * 8;
            const uint32_t kbn = smb + (FH_PS_HALVES + ((kb + 1) & 1) * FH_STG_HALVES) * 2;
            const uint32_t vbn = kbn + 64 * FH_LD * 2;
#pragma unroll
            for (int j = 0; j < 2; j++) {
                const int r = lrk + 32 * j;
                cp16(kbn + (r * FH_LD + lck) * 2,
                     K + baseh + (size_t)(kv0 + 64 + r) * DMODEL + lck);
                cp16(vbn + (r * FH_LD + lck) * 2,
                     Vt + vbase + (size_t)r * SEQ + kv0 + 64 + lck);
            }
            CP_COMMIT();
        }

        const uint32_t ksb = smb + (FH_PS_HALVES + (kb & 1) * FH_STG_HALVES) * 2;
        const uint32_t vsb = ksb + 64 * FH_LD * 2;

        if (kv0 + co <= rmin + 31) {   // warp's kv-half intersects causal region
            // --- S = Q @ K^T (only this warp's 32 kv columns) ---
            float sf[2][4][4];
#pragma unroll
            for (int mt = 0; mt < 2; mt++)
#pragma unroll
                for (int nt = 0; nt < 4; nt++)
#pragma unroll
                    for (int r = 0; r < 4; r++) sf[mt][nt][r] = 0.0f;

#pragma unroll
            for (int ks = 0; ks < 4; ks++) {
                uint32_t bf[4][2];
#pragma unroll
                for (int p = 0; p < 2; p++) {
                    const uint32_t addr = ksb + (co + p * 16 + lm_row) * FH_LDB
                                        + ks * 32 + lm_koff;
                    ldsm_x4(bf[2 * p][0], bf[2 * p][1],
                            bf[2 * p + 1][0], bf[2 * p + 1][1], addr);
                }
#pragma unroll
                for (int mt = 0; mt < 2; mt++)
#pragma unroll
                    for (int nt = 0; nt < 4; nt++)
                        mma_f16(sf[mt][nt][0], sf[mt][nt][1],
                                sf[mt][nt][2], sf[mt][nt][3],
                                qf[mt][ks][0], qf[mt][ks][1],
                                qf[mt][ks][2], qf[mt][ks][3],
                                bf[nt][0], bf[nt][1]);
            }

            // --- causal mask (diag band only) ---
            if (kv0 + co + 31 > rmin) {
#pragma unroll
                for (int mt = 0; mt < 2; mt++) {
                    const int r0 = rmin + mt * 16 + g, r1 = r0 + 8;
#pragma unroll
                    for (int nt = 0; nt < 4; nt++) {
                        const int c0 = kv0 + co + nt * 8 + 2 * q, c1 = c0 + 1;
                        if (c0 > r0) sf[mt][nt][0] = MASKV;
                        if (c1 > r0) sf[mt][nt][1] = MASKV;
                        if (c0 > r1) sf[mt][nt][2] = MASKV;
                        if (c1 > r1) sf[mt][nt][3] = MASKV;
                    }
                }
            }

            // --- per-warp online softmax over this warp's half ---
            uint32_t pf[2][4][2];
#pragma unroll
            for (int mt = 0; mt < 2; mt++) {
                float mx0 = MASKV, mx1 = MASKV;
#pragma unroll
                for (int nt = 0; nt < 4; nt++) {
                    mx0 = fmaxf(mx0, fmaxf(sf[mt][nt][0], sf[mt][nt][1]));
                    mx1 = fmaxf(mx1, fmaxf(sf[mt][nt][2], sf[mt][nt][3]));
                }
                mx0 = fmaxf(mx0, __shfl_xor_sync(0xffffffffu, mx0, 1));
                mx0 = fmaxf(mx0, __shfl_xor_sync(0xffffffffu, mx0, 2));
                mx1 = fmaxf(mx1, __shfl_xor_sync(0xffffffffu, mx1, 1));
                mx1 = fmaxf(mx1, __shfl_xor_sync(0xffffffffu, mx1, 2));

                const float mn0 = fmaxf(m[mt][0], mx0);
                const float mn1 = fmaxf(m[mt][1], mx1);
                const float al0 = exp2f(m[mt][0] - mn0);
                const float al1 = exp2f(m[mt][1] - mn1);
                m[mt][0] = mn0; m[mt][1] = mn1;

#pragma unroll
                for (int nt = 0; nt < 4; nt++) {
                    pf[mt][nt][0] = ex2_h2(h2u(__floats2half2_rn(
                        sf[mt][nt][0] - mn0, sf[mt][nt][1] - mn0)));
                    pf[mt][nt][1] = ex2_h2(h2u(__floats2half2_rn(
                        sf[mt][nt][2] - mn1, sf[mt][nt][3] - mn1)));
                }
#pragma unroll
                for (int nt = 0; nt < 8; nt++) {
                    acc[mt][nt][0] *= al0; acc[mt][nt][1] *= al0;
                    acc[mt][nt][2] *= al1; acc[mt][nt][3] *= al1;
                }
                lacc[mt][0] *= al0; lacc[mt][1] *= al0;
                lacc[mt][2] *= al1; lacc[mt][3] *= al1;
            }

            // --- O += P @ V ; l += P @ ones (kv-half, 2 k16 chunks) ---
#pragma unroll
            for (int ks = 0; ks < 2; ks++) {
                uint32_t bf[8][2];
#pragma unroll
                for (int p = 0; p < 4; p++) {
                    const uint32_t addr = vsb + (p * 16 + lm_row) * FH_LDB
                                        + co * 2 + ks * 32 + lm_koff;
                    ldsm_x4(bf[2 * p][0], bf[2 * p][1],
                            bf[2 * p + 1][0], bf[2 * p + 1][1], addr);
                }
#pragma unroll
                for (int mt = 0; mt < 2; mt++) {
                    const uint32_t a0 = pf[mt][2 * ks][0];
                    const uint32_t a1 = pf[mt][2 * ks][1];
                    const uint32_t a2 = pf[mt][2 * ks + 1][0];
                    const uint32_t a3 = pf[mt][2 * ks + 1][1];
#pragma unroll
                    for (int nt = 0; nt < 8; nt++)
                        mma_f16(acc[mt][nt][0], acc[mt][nt][1],
                                acc[mt][nt][2], acc[mt][nt][3],
                                a0, a1, a2, a3, bf[nt][0], bf[nt][1]);
                    mma_f16(lacc[mt][0], lacc[mt][1], lacc[mt][2], lacc[mt][3],
                            a0, a1, a2, a3, ONES_H2, ONES_H2);
                }
            }
        }

        CP_WAIT0();        // next tile's data landed
        __syncthreads();   // stage reuse barrier (1 per tile)
    }

    // --- pair reduction with max reconciliation ---
    float* red = (float*)sh;   // 4 groups x 32 lanes x 72 floats = 36864 B
    float* mine = red + (rg * 32 + lane) * 72;
    if (kvh) {
#pragma unroll
        for (int mt = 0; mt < 2; mt++) {
#pragma unroll
            for (int nt = 0; nt < 8; nt++)
                *(float4*)(mine + (mt * 8 + nt) * 4) =
                    make_float4(acc[mt][nt][0], acc[mt][nt][1],
                                acc[mt][nt][2], acc[mt][nt][3]);
            mine[64 + mt * 2 + 0] = lacc[mt][0];
            mine[64 + mt * 2 + 1] = lacc[mt][2];
            mine[68 + mt * 2 + 0] = m[mt][0];
            mine[68 + mt * 2 + 1] = m[mt][1];
        }
    }
    __syncthreads();
    if (!kvh) {
#pragma unroll
        for (int mt = 0; mt < 2; mt++) {
            const float lo0 = mine[64 + mt * 2 + 0];
            const float lo1 = mine[64 + mt * 2 + 1];
            const float mo0 = mine[68 + mt * 2 + 0];
            const float mo1 = mine[68 + mt * 2 + 1];
            const float M0 = fmaxf(m[mt][0], mo0);
            const float M1 = fmaxf(m[mt][1], mo1);
            const float es0 = exp2f(m[mt][0] - M0), eo0 = exp2f(mo0 - M0);
            const float es1 = exp2f(m[mt][1] - M1), eo1 = exp2f(mo1 - M1);
            const float inv0 = 1.0f / (lacc[mt][0] * es0 + lo0 * eo0);
            const float inv1 = 1.0f / (lacc[mt][2] * es1 + lo1 * eo1);
            const int r0 = q0 + rg * 32 + mt * 16 + g;
#pragma unroll
            for (int nt = 0; nt < 8; nt++) {
                float4 t = *(const float4*)(mine + (mt * 8 + nt) * 4);
                const int col = nt * 8 + 2 * q;
                *(__half2*)(O + baseh + (size_t)r0 * DMODEL + col) =
                    __floats2half2_rn((acc[mt][nt][0] * es0 + t.x * eo0) * inv0,
                                      (acc[mt][nt][1] * es0 + t.y * eo0) * inv0);
                *(__half2*)(O + baseh + (size_t)(r0 + 8) * DMODEL + col) =
                    __floats2half2_rn((acc[mt][nt][2] * es1 + t.z * eo1) * inv1,
                                      (acc[mt][nt][3] * es1 + t.w * eo1) * inv1);
            }
        }
    }
}

// ---------------------------------------------------------------------------
// Launch
// ---------------------------------------------------------------------------
extern "C" void kernel_launch(void* const* d_in, const int* in_sizes, int n_in,
                              void* d_out, int out_size)
{
    const float* x  = (const float*)d_in[0];
    const float* Wq = (const float*)d_in[1];
    const float* Wk = (const float*)d_in[2];
    const float* Wv = (const float*)d_in[3];
    const float* Wo = (const float*)d_in[4];
    float* out = (float*)d_out;

    __half *xh, *wh, *qb, *kb, *vb, *ab;
    cudaGetSymbolAddress((void**)&xh, g_xh);
    cudaGetSymbolAddress((void**)&wh, g_wh);
    cudaGetSymbolAddress((void**)&qb, g_q);
    cudaGetSymbolAddress((void**)&kb, g_k);
    cudaGetSymbolAddress((void**)&vb, g_v);
    cudaGetSymbolAddress((void**)&ab, g_a);

    cudaFuncSetAttribute(gemm_qkv,
                         cudaFuncAttributeMaxDynamicSharedMemorySize, GEMM_SMEM);
    cudaFuncSetAttribute(gemm_out,
                         cudaFuncAttributeMaxDynamicSharedMemorySize, GEMM_SMEM);
    cudaFuncSetAttribute(flash_attn_f16,
                         cudaFuncAttributeMaxDynamicSharedMemorySize, FA_SMEM);

    // --- prepass: fp32 -> fp16 for x and all weights ---
    f2h<<<MROWS * DMODEL / 2048, 256>>>(x, xh, MROWS * DMODEL);
    f2h4<<<dim3(DMODEL * DMODEL / 2048, 4), 256>>>(Wq, Wk, Wv, Wo, wh);

    // softmax scale folds 1/sqrt(dk) and log2(e) (flash runs in exp2 domain)
    const float qscale = 0.125f * 1.4426950408889634f;

    // --- fused QKV projections (grid.z = 3) ---
    gemm_qkv<<<dim3(DMODEL / 128, MROWS / 128, 3), 256, GEMM_SMEM>>>(
        xh, wh, qb, kb, vb, qscale);

    flash_attn_f16<<<dim3(SEQ / 128, NHEAD, BSZ), 256, FA_SMEM>>>(qb, kb, vb, ab);

    gemm_out<<<dim3(DMODEL / 128, MROWS / 128), 256, GEMM_SMEM>>>(
        ab, wh + (size_t)3 * DMODEL * DMODEL, out);
}

// round 16
// speedup vs baseline: 1.0217x; 1.0217x over previous
#include <cuda_runtime.h>
#include <cuda_fp16.h>
#include <cstdint>

#define BSZ    2
#define SEQ    2048
#define DMODEL 1024
#define NHEAD  16
#define DKH    64
#define MROWS  (BSZ * SEQ)   // 4096

// Scratch (allocation-free rule: __device__ globals). All fp16.
__device__ __half g_xh[MROWS * DMODEL];          // x in half
__device__ __half g_wh[4 * DMODEL * DMODEL];     // Wq,Wk,Wv,Wo in half
__device__ __half g_q[MROWS * DMODEL];           // q (scaled)
__device__ __half g_k[MROWS * DMODEL];           // k
__device__ __half g_v[MROWS * DMODEL];           // vt[b][h][64][2048]
__device__ __half g_a[MROWS * DMODEL];           // attention output (half)

// ---------------------------------------------------------------------------
// helpers (sm_80+ features only — the build targets plain sm_103)
// ---------------------------------------------------------------------------
__device__ __forceinline__ void mma_f16(
    float& d0, float& d1, float& d2, float& d3,
    uint32_t a0, uint32_t a1, uint32_t a2, uint32_t a3,
    uint32_t b0, uint32_t b1)
{
    asm volatile(
        "mma.sync.aligned.m16n8k16.row.col.f32.f16.f16.f32 "
        "{%0,%1,%2,%3}, {%4,%5,%6,%7}, {%8,%9}, {%0,%1,%2,%3};"
        : "+f"(d0), "+f"(d1), "+f"(d2), "+f"(d3)
        : "r"(a0), "r"(a1), "r"(a2), "r"(a3), "r"(b0), "r"(b1));
}

__device__ __forceinline__ void ldsm_x4(
    uint32_t& r0, uint32_t& r1, uint32_t& r2, uint32_t& r3, uint32_t addr)
{
    asm volatile("ldmatrix.sync.aligned.m8n8.x4.shared.b16 {%0,%1,%2,%3}, [%4];"
                 : "=r"(r0), "=r"(r1), "=r"(r2), "=r"(r3) : "r"(addr));
}

__device__ __forceinline__ uint32_t smem_u32(const void* p) {
    uint32_t a;
    asm("{ .reg .u64 t; cvta.to.shared.u64 t, %1; cvt.u32.u64 %0, t; }"
        : "=r"(a) : "l"(p));
    return a;
}

__device__ __forceinline__ uint32_t h2u(__half2 h) {
    return *reinterpret_cast<uint32_t*>(&h);
}

// packed half2 exp2 (sm_75+): one MUFU op per pair
__device__ __forceinline__ uint32_t ex2_h2(uint32_t x) {
    uint32_t r;
    asm("ex2.approx.f16x2 %0, %1;" : "=r"(r) : "r"(x));
    return r;
}

__device__ __forceinline__ void cp16(uint32_t dst, const void* src) {
    asm volatile("cp.async.ca.shared.global [%0], [%1], 16;"
                 :: "r"(dst), "l"(src) : "memory");
}
#define CP_COMMIT() asm volatile("cp.async.commit_group;" ::: "memory")
#define CP_WAIT0()  asm volatile("cp.async.wait_group 0;" ::: "memory")

// ---------------------------------------------------------------------------
// Prepass: fp32 -> fp16 conversion (producer-side; enables cp.async loaders)
// ---------------------------------------------------------------------------
__global__ __launch_bounds__(256) void f2h(
    const float* __restrict__ s, __half* __restrict__ d, int n)
{
    const int i = (blockIdx.x * 256 + threadIdx.x) * 8;
    if (i < n) {
        float4 a = *(const float4*)(s + i);
        float4 b = *(const float4*)(s + i + 4);
        union { __half2 h[4]; uint4 u; } u;
        u.h[0] = __floats2half2_rn(a.x, a.y);
        u.h[1] = __floats2half2_rn(a.z, a.w);
        u.h[2] = __floats2half2_rn(b.x, b.y);
        u.h[3] = __floats2half2_rn(b.z, b.w);
        *(uint4*)(d + i) = u.u;
    }
}

__global__ __launch_bounds__(256) void f2h4(
    const float* __restrict__ w0, const float* __restrict__ w1,
    const float* __restrict__ w2, const float* __restrict__ w3,
    __half* __restrict__ d)
{
    const float* srcs[4] = {w0, w1, w2, w3};
    const float* s = srcs[blockIdx.y];
    __half* dd = d + (size_t)blockIdx.y * DMODEL * DMODEL;
    const int i = (blockIdx.x * 256 + threadIdx.x) * 8;
    float4 a = *(const float4*)(s + i);
    float4 b = *(const float4*)(s + i + 4);
    union { __half2 h[4]; uint4 u; } u;
    u.h[0] = __floats2half2_rn(a.x, a.y);
    u.h[1] = __floats2half2_rn(a.z, a.w);
    u.h[2] = __floats2half2_rn(b.x, b.y);
    u.h[3] = __floats2half2_rn(b.z, b.w);
    *(uint4*)(dd + i) = u.u;
}

// ---------------------------------------------------------------------------
// fp16 GEMM NT body (unchanged — validated)
// ---------------------------------------------------------------------------
#define GEMM_SMEM (2 * 32768)   // 65536 B

__device__ __forceinline__ void gemm_body(
    const __half* __restrict__ A, const __half* __restrict__ W,
    void* __restrict__ Cv, float oscale, int mode, char* smg)
{
    const int tid  = threadIdx.x;
    const int lane = tid & 31;
    const int wm   = (tid >> 5) & 3;
    const int wn   = tid >> 7;
    const int m0 = blockIdx.y * 128;
    const int n0 = blockIdx.x * 128;
    const uint32_t smb = smem_u32(smg);

    const int lr  = tid >> 1;
    const int lc4 = (tid & 1) * 4;
    const __half* Ag = A + (size_t)(m0 + lr) * DMODEL + lc4 * 8;
    const __half* Wg = W + (size_t)(n0 + lr) * DMODEL + lc4 * 8;
    const uint32_t sBase = lc4 * 2048 + lr * 16;

    float acc[2][8][4];
#pragma unroll
    for (int i = 0; i < 2; i++)
#pragma unroll
        for (int j = 0; j < 8; j++)
#pragma unroll
            for (int r = 0; r < 4; r++) acc[i][j][r] = 0.0f;

    const int NCH = DMODEL / 64;   // 16

#pragma unroll
    for (int j = 0; j < 4; j++) {
        cp16(smb + sBase + j * 2048,         Ag + j * 8);
        cp16(smb + 16384 + sBase + j * 2048, Wg + j * 8);
    }
    CP_COMMIT();

    for (int s = 0; s < NCH; s++) {
        CP_WAIT0();
        __syncthreads();

        if (s + 1 < NCH) {
            const uint32_t st = smb + ((s + 1) & 1) * 32768;
            const int k0 = (s + 1) * 64;
#pragma unroll
            for (int j = 0; j < 4; j++) {
                cp16(st + sBase + j * 2048,         Ag + k0 + j * 8);
                cp16(st + 16384 + sBase + j * 2048, Wg + k0 + j * 8);
            }
            CP_COMMIT();
        }

        const uint32_t st = smb + (s & 1) * 32768;
#pragma unroll
        for (int ks = 0; ks < 4; ks++) {
            uint32_t af[2][4];
            uint32_t bf[8][2];
#pragma unroll
            for (int mt = 0; mt < 2; mt++) {
                const uint32_t addr = st + (2 * ks + (lane >> 4)) * 2048
                                    + (wm * 32 + mt * 16 + (lane & 15)) * 16;
                ldsm_x4(af[mt][0], af[mt][1], af[mt][2], af[mt][3], addr);
            }
#pragma unroll
            for (int p = 0; p < 4; p++) {
                const uint32_t addr = st + 16384 + (2 * ks + ((lane >> 3) & 1)) * 2048
                                    + (wn * 64 + p * 16 + ((lane >> 4) << 3) + (lane & 7)) * 16;
                ldsm_x4(bf[2 * p][0], bf[2 * p][1], bf[2 * p + 1][0], bf[2 * p + 1][1], addr);
            }
#pragma unroll
            for (int mt = 0; mt < 2; mt++)
#pragma unroll
                for (int nt = 0; nt < 8; nt++)
                    mma_f16(acc[mt][nt][0], acc[mt][nt][1],
                            acc[mt][nt][2], acc[mt][nt][3],
                            af[mt][0], af[mt][1], af[mt][2], af[mt][3],
                            bf[nt][0], bf[nt][1]);
        }
    }

    const int g = lane >> 2, q = lane & 3;
#pragma unroll
    for (int mt = 0; mt < 2; mt++) {
        const int mrow = m0 + wm * 32 + mt * 16 + g;
#pragma unroll
        for (int nt = 0; nt < 8; nt++) {
            const int ncol = n0 + wn * 64 + nt * 8 + 2 * q;
            if (mode == 0) {
                float* C = (float*)Cv;
                *(float2*)(C + (size_t)mrow * DMODEL + ncol) =
                    make_float2(acc[mt][nt][0], acc[mt][nt][1]);
                *(float2*)(C + (size_t)(mrow + 8) * DMODEL + ncol) =
                    make_float2(acc[mt][nt][2], acc[mt][nt][3]);
            } else if (mode == 1) {
                __half2* C = (__half2*)Cv;
                C[((size_t)mrow * DMODEL + ncol) >> 1] =
                    __floats2half2_rn(acc[mt][nt][0] * oscale, acc[mt][nt][1] * oscale);
                C[((size_t)(mrow + 8) * DMODEL + ncol) >> 1] =
                    __floats2half2_rn(acc[mt][nt][2] * oscale, acc[mt][nt][3] * oscale);
            } else {
                // vt[((b*NHEAD + h)*64 + d) * SEQ + s]
                __half* C = (__half*)Cv;
                const int h = ncol >> 6, d = ncol & 63;
                const size_t hb = ((size_t)((mrow >> 11) * NHEAD + h) * 64);
                const int s0 = mrow & 2047;
                C[(hb + d)     * SEQ + s0]     = __float2half_rn(acc[mt][nt][0]);
                C[(hb + d + 1) * SEQ + s0]     = __float2half_rn(acc[mt][nt][1]);
                C[(hb + d)     * SEQ + s0 + 8] = __float2half_rn(acc[mt][nt][2]);
                C[(hb + d + 1) * SEQ + s0 + 8] = __float2half_rn(acc[mt][nt][3]);
            }
        }
    }
}

__global__ __launch_bounds__(256, 2) void gemm_qkv(
    const __half* __restrict__ xh, const __half* __restrict__ wh,
    __half* __restrict__ qb, __half* __restrict__ kb, __half* __restrict__ vb,
    float qscale)
{
    extern __shared__ char smg[];
    const int z = blockIdx.z;
    const __half* W = wh + (size_t)z * DMODEL * DMODEL;
    void* C   = (z == 0) ? (void*)qb : (z == 1) ? (void*)kb : (void*)vb;
    const float sc = (z == 0) ? qscale : 1.0f;
    const int mode = (z == 2) ? 2 : 1;
    gemm_body(xh, W, C, sc, mode, smg);
}

__global__ __launch_bounds__(256, 2) void gemm_out(
    const __half* __restrict__ A, const __half* __restrict__ W,
    float* __restrict__ C)
{
    extern __shared__ char smg[];
    gemm_body(A, W, C, 1.0f, 0, smg);
}

// ---------------------------------------------------------------------------
// fp16 flash attention (causal), warp-pair KV split + per-warp online softmax,
// repackaged as 128-thread CTAs (BQ=64, 2 row-groups x 32 rows) so TWO CTAs
// fit per SM (196 regs x 128 thr x 2 = 50K < 64K): same 8 warps/SM as the
// 256-thread version but with decorrelated per-CTA barriers -> issue slots
// stay filled while one CTA sits at its tile barrier / softmax chain.
// ---------------------------------------------------------------------------
#define FH_LD        72
#define FH_LDB       (FH_LD * 2)              // 144 bytes per row
#define FH_PS_HALVES (64 * FH_LD)             // 4608 (Q staging, 64 rows)
#define FH_STG_HALVES (2 * 64 * FH_LD)        // 9216 (K + V)
#define FA_SMEM ((FH_PS_HALVES + 2 * FH_STG_HALVES) * 2)   // 46080 B
#define ONES_H2 0x3C003C00u                   // half2(1.0, 1.0)
#define MINIT   (-100.0f)
#define MASKV   (-1e30f)

__global__ __launch_bounds__(128, 2) void flash_attn_f16(
    const __half* __restrict__ Q, const __half* __restrict__ K,
    const __half* __restrict__ Vt, __half* __restrict__ O)
{
    extern __shared__ __half sh[];

    const int tid  = threadIdx.x;
    const int w    = tid >> 5;        // 0..3
    const int lane = tid & 31;
    const int g    = lane >> 2;
    const int q    = lane & 3;
    const int rg   = w >> 1;          // row group 0..1 (32 rows each)
    const int kvh  = w & 1;           // which KV half this warp owns
    const int co   = kvh * 32;        // kv column offset
    const int qb = gridDim.x - 1 - blockIdx.x;   // reversed: longest first
    const int h  = blockIdx.y, b = blockIdx.z;
    const int q0 = qb * 64;
    const size_t baseh = (size_t)b * SEQ * DMODEL + (size_t)h * DKH;
    const size_t vbase = ((size_t)(b * NHEAD + h)) * 64 * SEQ;

    const uint32_t smb = smem_u32(sh);
    const uint32_t lm_row = ((lane >> 4) << 3) + (lane & 7);
    const uint32_t lm_koff = ((lane >> 3) & 1) * 16;

    const int ntiles = qb + 1;

    // --- prologue: async-stage Q (64 rows x 128B) and KV tile 0 ---
    for (int i = tid; i < 64 * 8; i += 128) {
        const int r = i >> 3, c = (i & 7) * 8;
        cp16(smb + (r * FH_LD + c) * 2, Q + baseh + (size_t)(q0 + r) * DMODEL + c);
    }
    {
        const int lrk = tid >> 3, lck = (tid & 7) * 8;   // 16 rows x 8 chunks
        const uint32_t kb0 = smb + FH_PS_HALVES * 2;
        const uint32_t vb0 = kb0 + 64 * FH_LD * 2;
#pragma unroll
        for (int j = 0; j < 4; j++) {
            const int r = lrk + 16 * j;
            cp16(kb0 + (r * FH_LD + lck) * 2, K + baseh + (size_t)r * DMODEL + lck);
            cp16(vb0 + (r * FH_LD + lck) * 2, Vt + vbase + (size_t)r * SEQ + lck);
        }
    }
    CP_COMMIT();
    CP_WAIT0();
    __syncthreads();

    // --- lift Q (rows rg*32 .. +31) into register fragments qf[mt][ks][4] ---
    uint32_t qf[2][4][4];
#pragma unroll
    for (int mt = 0; mt < 2; mt++) {
        const uint32_t* r0p = (const uint32_t*)sh + (rg * 32 + mt * 16 + g) * 36;
        const uint32_t* r1p = r0p + 8 * 36;
#pragma unroll
        for (int ks = 0; ks < 4; ks++) {
            qf[mt][ks][0] = r0p[ks * 8 + q];
            qf[mt][ks][1] = r1p[ks * 8 + q];
            qf[mt][ks][2] = r0p[ks * 8 + q + 4];
            qf[mt][ks][3] = r1p[ks * 8 + q + 4];
        }
    }

    float acc[2][8][4];
    float lacc[2][4];
    float m[2][2];                    // running max: [mt][row-half (g / g+8)]
#pragma unroll
    for (int mt = 0; mt < 2; mt++) {
#pragma unroll
        for (int nt = 0; nt < 8; nt++)
#pragma unroll
            for (int r = 0; r < 4; r++) acc[mt][nt][r] = 0.0f;
#pragma unroll
        for (int r = 0; r < 4; r++) lacc[mt][r] = 0.0f;
        m[mt][0] = MINIT; m[mt][1] = MINIT;
    }

    const int rmin = q0 + rg * 32;    // warp's first query row

    for (int kb = 0; kb < ntiles; kb++) {
        const int kv0 = kb * 64;

        // --- issue cp.async for next tile into the other stage ---
        if (kb + 1 < ntiles) {
            const int lrk = tid >> 3, lck = (tid & 7) * 8;
            const uint32_t kbn = smb + (FH_PS_HALVES + ((kb + 1) & 1) * FH_STG_HALVES) * 2;
            const uint32_t vbn = kbn + 64 * FH_LD * 2;
#pragma unroll
            for (int j = 0; j < 4; j++) {
                const int r = lrk + 16 * j;
                cp16(kbn + (r * FH_LD + lck) * 2,
                     K + baseh + (size_t)(kv0 + 64 + r) * DMODEL + lck);
                cp16(vbn + (r * FH_LD + lck) * 2,
                     Vt + vbase + (size_t)r * SEQ + kv0 + 64 + lck);
            }
            CP_COMMIT();
        }

        const uint32_t ksb = smb + (FH_PS_HALVES + (kb & 1) * FH_STG_HALVES) * 2;
        const uint32_t vsb = ksb + 64 * FH_LD * 2;

        if (kv0 + co <= rmin + 31) {   // warp's kv-half intersects causal region
            // --- S = Q @ K^T (only this warp's 32 kv columns) ---
            float sf[2][4][4];
#pragma unroll
            for (int mt = 0; mt < 2; mt++)
#pragma unroll
                for (int nt = 0; nt < 4; nt++)
#pragma unroll
                    for (int r = 0; r < 4; r++) sf[mt][nt][r] = 0.0f;

#pragma unroll
            for (int ks = 0; ks < 4; ks++) {
                uint32_t bf[4][2];
#pragma unroll
                for (int p = 0; p < 2; p++) {
                    const uint32_t addr = ksb + (co + p * 16 + lm_row) * FH_LDB
                                        + ks * 32 + lm_koff;
                    ldsm_x4(bf[2 * p][0], bf[2 * p][1],
                            bf[2 * p + 1][0], bf[2 * p + 1][1], addr);
                }
#pragma unroll
                for (int mt = 0; mt < 2; mt++)
#pragma unroll
                    for (int nt = 0; nt < 4; nt++)
                        mma_f16(sf[mt][nt][0], sf[mt][nt][1],
                                sf[mt][nt][2], sf[mt][nt][3],
                                qf[mt][ks][0], qf[mt][ks][1],
                                qf[mt][ks][2], qf[mt][ks][3],
                                bf[nt][0], bf[nt][1]);
            }

            // --- causal mask (diag band only) ---
            if (kv0 + co + 31 > rmin) {
#pragma unroll
                for (int mt = 0; mt < 2; mt++) {
                    const int r0 = rmin + mt * 16 + g, r1 = r0 + 8;
#pragma unroll
                    for (int nt = 0; nt < 4; nt++) {
                        const int c0 = kv0 + co + nt * 8 + 2 * q, c1 = c0 + 1;
                        if (c0 > r0) sf[mt][nt][0] = MASKV;
                        if (c1 > r0) sf[mt][nt][1] = MASKV;
                        if (c0 > r1) sf[mt][nt][2] = MASKV;
                        if (c1 > r1) sf[mt][nt][3] = MASKV;
                    }
                }
            }

            // --- per-warp online softmax over this warp's half ---
            uint32_t pf[2][4][2];
#pragma unroll
            for (int mt = 0; mt < 2; mt++) {
                float mx0 = MASKV, mx1 = MASKV;
#pragma unroll
                for (int nt = 0; nt < 4; nt++) {
                    mx0 = fmaxf(mx0, fmaxf(sf[mt][nt][0], sf[mt][nt][1]));
                    mx1 = fmaxf(mx1, fmaxf(sf[mt][nt][2], sf[mt][nt][3]));
                }
                mx0 = fmaxf(mx0, __shfl_xor_sync(0xffffffffu, mx0, 1));
                mx0 = fmaxf(mx0, __shfl_xor_sync(0xffffffffu, mx0, 2));
                mx1 = fmaxf(mx1, __shfl_xor_sync(0xffffffffu, mx1, 1));
                mx1 = fmaxf(mx1, __shfl_xor_sync(0xffffffffu, mx1, 2));

                const float mn0 = fmaxf(m[mt][0], mx0);
                const float mn1 = fmaxf(m[mt][1], mx1);
                const float al0 = exp2f(m[mt][0] - mn0);
                const float al1 = exp2f(m[mt][1] - mn1);
                m[mt][0] = mn0; m[mt][1] = mn1;

#pragma unroll
                for (int nt = 0; nt < 4; nt++) {
                    pf[mt][nt][0] = ex2_h2(h2u(__floats2half2_rn(
                        sf[mt][nt][0] - mn0, sf[mt][nt][1] - mn0)));
                    pf[mt][nt][1] = ex2_h2(h2u(__floats2half2_rn(
                        sf[mt][nt][2] - mn1, sf[mt][nt][3] - mn1)));
                }
#pragma unroll
                for (int nt = 0; nt < 8; nt++) {
                    acc[mt][nt][0] *= al0; acc[mt][nt][1] *= al0;
                    acc[mt][nt][2] *= al1; acc[mt][nt][3] *= al1;
                }
                lacc[mt][0] *= al0; lacc[mt][1] *= al0;
                lacc[mt][2] *= al1; lacc[mt][3] *= al1;
            }

            // --- O += P @ V ; l += P @ ones (kv-half, 2 k16 chunks) ---
#pragma unroll
            for (int ks = 0; ks < 2; ks++) {
                uint32_t bf[8][2];
#pragma unroll
                for (int p = 0; p < 4; p++) {
                    const uint32_t addr = vsb + (p * 16 + lm_row) * FH_LDB
                                        + co * 2 + ks * 32 + lm_koff;
                    ldsm_x4(bf[2 * p][0], bf[2 * p][1],
                            bf[2 * p + 1][0], bf[2 * p + 1][1], addr);
                }
#pragma unroll
                for (int mt = 0; mt < 2; mt++) {
                    const uint32_t a0 = pf[mt][2 * ks][0];
                    const uint32_t a1 = pf[mt][2 * ks][1];
                    const uint32_t a2 = pf[mt][2 * ks + 1][0];
                    const uint32_t a3 = pf[mt][2 * ks + 1][1];
#pragma unroll
                    for (int nt = 0; nt < 8; nt++)
                        mma_f16(acc[mt][nt][0], acc[mt][nt][1],
                                acc[mt][nt][2], acc[mt][nt][3],
                                a0, a1, a2, a3, bf[nt][0], bf[nt][1]);
                    mma_f16(lacc[mt][0], lacc[mt][1], lacc[mt][2], lacc[mt][3],
                            a0, a1, a2, a3, ONES_H2, ONES_H2);
                }
            }
        }

        CP_WAIT0();        // next tile's data landed
        __syncthreads();   // stage reuse barrier (1 per tile)
    }

    // --- pair reduction with max reconciliation (reuses smem after barrier) ---
    float* red = (float*)sh;   // 2 groups x 32 lanes x 72 floats = 18432 B
    float* mine = red + (rg * 32 + lane) * 72;
    if (kvh) {
#pragma unroll
        for (int mt = 0; mt < 2; mt++) {
#pragma unroll
            for (int nt = 0; nt < 8; nt++)
                *(float4*)(mine + (mt * 8 + nt) * 4) =
                    make_float4(acc[mt][nt][0], acc[mt][nt][1],
                                acc[mt][nt][2], acc[mt][nt][3]);
            mine[64 + mt * 2 + 0] = lacc[mt][0];
            mine[64 + mt * 2 + 1] = lacc[mt][2];
            mine[68 + mt * 2 + 0] = m[mt][0];
            mine[68 + mt * 2 + 1] = m[mt][1];
        }
    }
    __syncthreads();
    if (!kvh) {
#pragma unroll
        for (int mt = 0; mt < 2; mt++) {
            const float lo0 = mine[64 + mt * 2 + 0];
            const float lo1 = mine[64 + mt * 2 + 1];
            const float mo0 = mine[68 + mt * 2 + 0];
            const float mo1 = mine[68 + mt * 2 + 1];
            const float M0 = fmaxf(m[mt][0], mo0);
            const float M1 = fmaxf(m[mt][1], mo1);
            const float es0 = exp2f(m[mt][0] - M0), eo0 = exp2f(mo0 - M0);
            const float es1 = exp2f(m[mt][1] - M1), eo1 = exp2f(mo1 - M1);
            const float inv0 = 1.0f / (lacc[mt][0] * es0 + lo0 * eo0);
            const float inv1 = 1.0f / (lacc[mt][2] * es1 + lo1 * eo1);
            const int r0 = q0 + rg * 32 + mt * 16 + g;
#pragma unroll
            for (int nt = 0; nt < 8; nt++) {
                float4 t = *(const float4*)(mine + (mt * 8 + nt) * 4);
                const int col = nt * 8 + 2 * q;
                *(__half2*)(O + baseh + (size_t)r0 * DMODEL + col) =
                    __floats2half2_rn((acc[mt][nt][0] * es0 + t.x * eo0) * inv0,
                                      (acc[mt][nt][1] * es0 + t.y * eo0) * inv0);
                *(__half2*)(O + baseh + (size_t)(r0 + 8) * DMODEL + col) =
                    __floats2half2_rn((acc[mt][nt][2] * es1 + t.z * eo1) * inv1,
                                      (acc[mt][nt][3] * es1 + t.w * eo1) * inv1);
            }
        }
    }
}

// ---------------------------------------------------------------------------
// Launch
// ---------------------------------------------------------------------------
extern "C" void kernel_launch(void* const* d_in, const int* in_sizes, int n_in,
                              void* d_out, int out_size)
{
    const float* x  = (const float*)d_in[0];
    const float* Wq = (const float*)d_in[1];
    const float* Wk = (const float*)d_in[2];
    const float* Wv = (const float*)d_in[3];
    const float* Wo = (const float*)d_in[4];
    float* out = (float*)d_out;

    __half *xh, *wh, *qb, *kb, *vb, *ab;
    cudaGetSymbolAddress((void**)&xh, g_xh);
    cudaGetSymbolAddress((void**)&wh, g_wh);
    cudaGetSymbolAddress((void**)&qb, g_q);
    cudaGetSymbolAddress((void**)&kb, g_k);
    cudaGetSymbolAddress((void**)&vb, g_v);
    cudaGetSymbolAddress((void**)&ab, g_a);

    cudaFuncSetAttribute(gemm_qkv,
                         cudaFuncAttributeMaxDynamicSharedMemorySize, GEMM_SMEM);
    cudaFuncSetAttribute(gemm_out,
                         cudaFuncAttributeMaxDynamicSharedMemorySize, GEMM_SMEM);
    cudaFuncSetAttribute(flash_attn_f16,
                         cudaFuncAttributeMaxDynamicSharedMemorySize, FA_SMEM);

    // --- prepass: fp32 -> fp16 for x and all weights ---
    f2h<<<MROWS * DMODEL / 2048, 256>>>(x, xh, MROWS * DMODEL);
    f2h4<<<dim3(DMODEL * DMODEL / 2048, 4), 256>>>(Wq, Wk, Wv, Wo, wh);

    // softmax scale folds 1/sqrt(dk) and log2(e) (flash runs in exp2 domain)
    const float qscale = 0.125f * 1.4426950408889634f;

    // --- fused QKV projections (grid.z = 3) ---
    gemm_qkv<<<dim3(DMODEL / 128, MROWS / 128, 3), 256, GEMM_SMEM>>>(
        xh, wh, qb, kb, vb, qscale);

    flash_attn_f16<<<dim3(SEQ / 64, NHEAD, BSZ), 128, FA_SMEM>>>(qb, kb, vb, ab);

    gemm_out<<<dim3(DMODEL / 128, MROWS / 128), 256, GEMM_SMEM>>>(
        ab, wh + (size_t)3 * DMODEL * DMODEL, out);
}

// round 17
// speedup vs baseline: 1.0323x; 1.0104x over previous
#include <cuda_runtime.h>
#include <cuda_fp16.h>
#include <cstdint>

#define BSZ    2
#define SEQ    2048
#define DMODEL 1024
#define NHEAD  16
#define DKH    64
#define MROWS  (BSZ * SEQ)   // 4096

// Scratch (allocation-free rule: __device__ globals). All fp16.
__device__ __half g_xh[MROWS * DMODEL];          // x in half
__device__ __half g_wh[4 * DMODEL * DMODEL];     // Wq,Wk,Wv,Wo in half
__device__ __half g_q[MROWS * DMODEL];           // q (scaled)
__device__ __half g_k[MROWS * DMODEL];           // k
__device__ __half g_v[MROWS * DMODEL];           // vt[b][h][64][2048]
__device__ __half g_a[MROWS * DMODEL];           // attention output (half)

// ---------------------------------------------------------------------------
// helpers (sm_80+ features only — the build targets plain sm_103)
// ---------------------------------------------------------------------------
__device__ __forceinline__ void mma_f16(
    float& d0, float& d1, float& d2, float& d3,
    uint32_t a0, uint32_t a1, uint32_t a2, uint32_t a3,
    uint32_t b0, uint32_t b1)
{
    asm volatile(
        "mma.sync.aligned.m16n8k16.row.col.f32.f16.f16.f32 "
        "{%0,%1,%2,%3}, {%4,%5,%6,%7}, {%8,%9}, {%0,%1,%2,%3};"
        : "+f"(d0), "+f"(d1), "+f"(d2), "+f"(d3)
        : "r"(a0), "r"(a1), "r"(a2), "r"(a3), "r"(b0), "r"(b1));
}

__device__ __forceinline__ void ldsm_x4(
    uint32_t& r0, uint32_t& r1, uint32_t& r2, uint32_t& r3, uint32_t addr)
{
    asm volatile("ldmatrix.sync.aligned.m8n8.x4.shared.b16 {%0,%1,%2,%3}, [%4];"
                 : "=r"(r0), "=r"(r1), "=r"(r2), "=r"(r3) : "r"(addr));
}

__device__ __forceinline__ uint32_t smem_u32(const void* p) {
    uint32_t a;
    asm("{ .reg .u64 t; cvta.to.shared.u64 t, %1; cvt.u32.u64 %0, t; }"
        : "=r"(a) : "l"(p));
    return a;
}

__device__ __forceinline__ uint32_t h2u(__half2 h) {
    return *reinterpret_cast<uint32_t*>(&h);
}

// packed half2 exp2 (sm_75+): one MUFU op per pair
__device__ __forceinline__ uint32_t ex2_h2(uint32_t x) {
    uint32_t r;
    asm("ex2.approx.f16x2 %0, %1;" : "=r"(r) : "r"(x));
    return r;
}

__device__ __forceinline__ void cp16(uint32_t dst, const void* src) {
    asm volatile("cp.async.ca.shared.global [%0], [%1], 16;"
                 :: "r"(dst), "l"(src) : "memory");
}
#define CP_COMMIT() asm volatile("cp.async.commit_group;" ::: "memory")
#define CP_WAIT0()  asm volatile("cp.async.wait_group 0;" ::: "memory")

// ---------------------------------------------------------------------------
// Prepass: fp32 -> fp16 conversion (producer-side; enables cp.async loaders)
// ---------------------------------------------------------------------------
__global__ __launch_bounds__(256) void f2h(
    const float* __restrict__ s, __half* __restrict__ d, int n)
{
    const int i = (blockIdx.x * 256 + threadIdx.x) * 8;
    if (i < n) {
        float4 a = *(const float4*)(s + i);
        float4 b = *(const float4*)(s + i + 4);
        union { __half2 h[4]; uint4 u; } u;
        u.h[0] = __floats2half2_rn(a.x, a.y);
        u.h[1] = __floats2half2_rn(a.z, a.w);
        u.h[2] = __floats2half2_rn(b.x, b.y);
        u.h[3] = __floats2half2_rn(b.z, b.w);
        *(uint4*)(d + i) = u.u;
    }
}

__global__ __launch_bounds__(256) void f2h4(
    const float* __restrict__ w0, const float* __restrict__ w1,
    const float* __restrict__ w2, const float* __restrict__ w3,
    __half* __restrict__ d)
{
    const float* srcs[4] = {w0, w1, w2, w3};
    const float* s = srcs[blockIdx.y];
    __half* dd = d + (size_t)blockIdx.y * DMODEL * DMODEL;
    const int i = (blockIdx.x * 256 + threadIdx.x) * 8;
    float4 a = *(const float4*)(s + i);
    float4 b = *(const float4*)(s + i + 4);
    union { __half2 h[4]; uint4 u; } u;
    u.h[0] = __floats2half2_rn(a.x, a.y);
    u.h[1] = __floats2half2_rn(a.z, a.w);
    u.h[2] = __floats2half2_rn(b.x, b.y);
    u.h[3] = __floats2half2_rn(b.z, b.w);
    *(uint4*)(dd + i) = u.u;
}

// ---------------------------------------------------------------------------
// fp16 GEMM NT body (unchanged — validated)
// ---------------------------------------------------------------------------
#define GEMM_SMEM (2 * 32768)   // 65536 B

__device__ __forceinline__ void gemm_body(
    const __half* __restrict__ A, const __half* __restrict__ W,
    void* __restrict__ Cv, float oscale, int mode, char* smg)
{
    const int tid  = threadIdx.x;
    const int lane = tid & 31;
    const int wm   = (tid >> 5) & 3;
    const int wn   = tid >> 7;
    const int m0 = blockIdx.y * 128;
    const int n0 = blockIdx.x * 128;
    const uint32_t smb = smem_u32(smg);

    const int lr  = tid >> 1;
    const int lc4 = (tid & 1) * 4;
    const __half* Ag = A + (size_t)(m0 + lr) * DMODEL + lc4 * 8;
    const __half* Wg = W + (size_t)(n0 + lr) * DMODEL + lc4 * 8;
    const uint32_t sBase = lc4 * 2048 + lr * 16;

    float acc[2][8][4];
#pragma unroll
    for (int i = 0; i < 2; i++)
#pragma unroll
        for (int j = 0; j < 8; j++)
#pragma unroll
            for (int r = 0; r < 4; r++) acc[i][j][r] = 0.0f;

    const int NCH = DMODEL / 64;   // 16

#pragma unroll
    for (int j = 0; j < 4; j++) {
        cp16(smb + sBase + j * 2048,         Ag + j * 8);
        cp16(smb + 16384 + sBase + j * 2048, Wg + j * 8);
    }
    CP_COMMIT();

    for (int s = 0; s < NCH; s++) {
        CP_WAIT0();
        __syncthreads();

        if (s + 1 < NCH) {
            const uint32_t st = smb + ((s + 1) & 1) * 32768;
            const int k0 = (s + 1) * 64;
#pragma unroll
            for (int j = 0; j < 4; j++) {
                cp16(st + sBase + j * 2048,         Ag + k0 + j * 8);
                cp16(st + 16384 + sBase + j * 2048, Wg + k0 + j * 8);
            }
            CP_COMMIT();
        }

        const uint32_t st = smb + (s & 1) * 32768;
#pragma unroll
        for (int ks = 0; ks < 4; ks++) {
            uint32_t af[2][4];
            uint32_t bf[8][2];
#pragma unroll
            for (int mt = 0; mt < 2; mt++) {
                const uint32_t addr = st + (2 * ks + (lane >> 4)) * 2048
                                    + (wm * 32 + mt * 16 + (lane & 15)) * 16;
                ldsm_x4(af[mt][0], af[mt][1], af[mt][2], af[mt][3], addr);
            }
#pragma unroll
            for (int p = 0; p < 4; p++) {
                const uint32_t addr = st + 16384 + (2 * ks + ((lane >> 3) & 1)) * 2048
                                    + (wn * 64 + p * 16 + ((lane >> 4) << 3) + (lane & 7)) * 16;
                ldsm_x4(bf[2 * p][0], bf[2 * p][1], bf[2 * p + 1][0], bf[2 * p + 1][1], addr);
            }
#pragma unroll
            for (int mt = 0; mt < 2; mt++)
#pragma unroll
                for (int nt = 0; nt < 8; nt++)
                    mma_f16(acc[mt][nt][0], acc[mt][nt][1],
                            acc[mt][nt][2], acc[mt][nt][3],
                            af[mt][0], af[mt][1], af[mt][2], af[mt][3],
                            bf[nt][0], bf[nt][1]);
        }
    }

    const int g = lane >> 2, q = lane & 3;
#pragma unroll
    for (int mt = 0; mt < 2; mt++) {
        const int mrow = m0 + wm * 32 + mt * 16 + g;
#pragma unroll
        for (int nt = 0; nt < 8; nt++) {
            const int ncol = n0 + wn * 64 + nt * 8 + 2 * q;
            if (mode == 0) {
                float* C = (float*)Cv;
                *(float2*)(C + (size_t)mrow * DMODEL + ncol) =
                    make_float2(acc[mt][nt][0], acc[mt][nt][1]);
                *(float2*)(C + (size_t)(mrow + 8) * DMODEL + ncol) =
                    make_float2(acc[mt][nt][2], acc[mt][nt][3]);
            } else if (mode == 1) {
                __half2* C = (__half2*)Cv;
                C[((size_t)mrow * DMODEL + ncol) >> 1] =
                    __floats2half2_rn(acc[mt][nt][0] * oscale, acc[mt][nt][1] * oscale);
                C[((size_t)(mrow + 8) * DMODEL + ncol) >> 1] =
                    __floats2half2_rn(acc[mt][nt][2] * oscale, acc[mt][nt][3] * oscale);
            } else {
                // vt[((b*NHEAD + h)*64 + d) * SEQ + s]
                __half* C = (__half*)Cv;
                const int h = ncol >> 6, d = ncol & 63;
                const size_t hb = ((size_t)((mrow >> 11) * NHEAD + h) * 64);
                const int s0 = mrow & 2047;
                C[(hb + d)     * SEQ + s0]     = __float2half_rn(acc[mt][nt][0]);
                C[(hb + d + 1) * SEQ + s0]     = __float2half_rn(acc[mt][nt][1]);
                C[(hb + d)     * SEQ + s0 + 8] = __float2half_rn(acc[mt][nt][2]);
                C[(hb + d + 1) * SEQ + s0 + 8] = __float2half_rn(acc[mt][nt][3]);
            }
        }
    }
}

__global__ __launch_bounds__(256, 2) void gemm_qkv(
    const __half* __restrict__ xh, const __half* __restrict__ wh,
    __half* __restrict__ qb, __half* __restrict__ kb, __half* __restrict__ vb,
    float qscale)
{
    extern __shared__ char smg[];
    const int z = blockIdx.z;
    const __half* W = wh + (size_t)z * DMODEL * DMODEL;
    void* C   = (z == 0) ? (void*)qb : (z == 1) ? (void*)kb : (void*)vb;
    const float sc = (z == 0) ? qscale : 1.0f;
    const int mode = (z == 2) ? 2 : 1;
    gemm_body(xh, W, C, sc, mode, smg);
}

__global__ __launch_bounds__(256, 2) void gemm_out(
    const __half* __restrict__ A, const __half* __restrict__ W,
    float* __restrict__ C)
{
    extern __shared__ char smg[];
    gemm_body(A, W, C, 1.0f, 0, smg);
}

// ---------------------------------------------------------------------------
// fp16 flash attention (causal), warp-pair KV split + per-warp online softmax.
// 128-thread CTAs (BQ=64), now __launch_bounds__(128, 3): reg cap 170 ->
// THREE independent CTAs per SM (12 warps) so per-CTA barrier/softmax chains
// overlap across CTAs. smem 3 x 46KB = 138KB < 228KB.
// ---------------------------------------------------------------------------
#define FH_LD        72
#define FH_LDB       (FH_LD * 2)              // 144 bytes per row
#define FH_PS_HALVES (64 * FH_LD)             // 4608 (Q staging, 64 rows)
#define FH_STG_HALVES (2 * 64 * FH_LD)        // 9216 (K + V)
#define FA_SMEM ((FH_PS_HALVES + 2 * FH_STG_HALVES) * 2)   // 46080 B
#define ONES_H2 0x3C003C00u                   // half2(1.0, 1.0)
#define MINIT   (-100.0f)
#define MASKV   (-1e30f)

__global__ __launch_bounds__(128, 3) void flash_attn_f16(
    const __half* __restrict__ Q, const __half* __restrict__ K,
    const __half* __restrict__ Vt, __half* __restrict__ O)
{
    extern __shared__ __half sh[];

    const int tid  = threadIdx.x;
    const int w    = tid >> 5;        // 0..3
    const int lane = tid & 31;
    const int g    = lane >> 2;
    const int q    = lane & 3;
    const int rg   = w >> 1;          // row group 0..1 (32 rows each)
    const int kvh  = w & 1;           // which KV half this warp owns
    const int co   = kvh * 32;        // kv column offset
    const int qb = gridDim.x - 1 - blockIdx.x;   // reversed: longest first
    const int h  = blockIdx.y, b = blockIdx.z;
    const int q0 = qb * 64;
    const size_t baseh = (size_t)b * SEQ * DMODEL + (size_t)h * DKH;
    const size_t vbase = ((size_t)(b * NHEAD + h)) * 64 * SEQ;

    const uint32_t smb = smem_u32(sh);
    const uint32_t lm_row = ((lane >> 4) << 3) + (lane & 7);
    const uint32_t lm_koff = ((lane >> 3) & 1) * 16;

    const int ntiles = qb + 1;

    // --- prologue: async-stage Q (64 rows x 128B) and KV tile 0 ---
    for (int i = tid; i < 64 * 8; i += 128) {
        const int r = i >> 3, c = (i & 7) * 8;
        cp16(smb + (r * FH_LD + c) * 2, Q + baseh + (size_t)(q0 + r) * DMODEL + c);
    }
    {
        const int lrk = tid >> 3, lck = (tid & 7) * 8;   // 16 rows x 8 chunks
        const uint32_t kb0 = smb + FH_PS_HALVES * 2;
        const uint32_t vb0 = kb0 + 64 * FH_LD * 2;
#pragma unroll
        for (int j = 0; j < 4; j++) {
            const int r = lrk + 16 * j;
            cp16(kb0 + (r * FH_LD + lck) * 2, K + baseh + (size_t)r * DMODEL + lck);
            cp16(vb0 + (r * FH_LD + lck) * 2, Vt + vbase + (size_t)r * SEQ + lck);
        }
    }
    CP_COMMIT();
    CP_WAIT0();
    __syncthreads();

    // --- lift Q (rows rg*32 .. +31) into register fragments qf[mt][ks][4] ---
    uint32_t qf[2][4][4];
#pragma unroll
    for (int mt = 0; mt < 2; mt++) {
        const uint32_t* r0p = (const uint32_t*)sh + (rg * 32 + mt * 16 + g) * 36;
        const uint32_t* r1p = r0p + 8 * 36;
#pragma unroll
        for (int ks = 0; ks < 4; ks++) {
            qf[mt][ks][0] = r0p[ks * 8 + q];
            qf[mt][ks][1] = r1p[ks * 8 + q];
            qf[mt][ks][2] = r0p[ks * 8 + q + 4];
            qf[mt][ks][3] = r1p[ks * 8 + q + 4];
        }
    }

    float acc[2][8][4];
    float lacc[2][4];
    float m[2][2];                    // running max: [mt][row-half (g / g+8)]
#pragma unroll
    for (int mt = 0; mt < 2; mt++) {
#pragma unroll
        for (int nt = 0; nt < 8; nt++)
#pragma unroll
            for (int r = 0; r < 4; r++) acc[mt][nt][r] = 0.0f;
#pragma unroll
        for (int r = 0; r < 4; r++) lacc[mt][r] = 0.0f;
        m[mt][0] = MINIT; m[mt][1] = MINIT;
    }

    const int rmin = q0 + rg * 32;    // warp's first query row

    for (int kb = 0; kb < ntiles; kb++) {
        const int kv0 = kb * 64;

        // --- issue cp.async for next tile into the other stage ---
        if (kb + 1 < ntiles) {
            const int lrk = tid >> 3, lck = (tid & 7) * 8;
            const uint32_t kbn = smb + (FH_PS_HALVES + ((kb + 1) & 1) * FH_STG_HALVES) * 2;
            const uint32_t vbn = kbn + 64 * FH_LD * 2;
#pragma unroll
            for (int j = 0; j < 4; j++) {
                const int r = lrk + 16 * j;
                cp16(kbn + (r * FH_LD + lck) * 2,
                     K + baseh + (size_t)(kv0 + 64 + r) * DMODEL + lck);
                cp16(vbn + (r * FH_LD + lck) * 2,
                     Vt + vbase + (size_t)r * SEQ + kv0 + 64 + lck);
            }
            CP_COMMIT();
        }

        const uint32_t ksb = smb + (FH_PS_HALVES + (kb & 1) * FH_STG_HALVES) * 2;
        const uint32_t vsb = ksb + 64 * FH_LD * 2;

        if (kv0 + co <= rmin + 31) {   // warp's kv-half intersects causal region
            // --- S = Q @ K^T (only this warp's 32 kv columns) ---
            float sf[2][4][4];
#pragma unroll
            for (int mt = 0; mt < 2; mt++)
#pragma unroll
                for (int nt = 0; nt < 4; nt++)
#pragma unroll
                    for (int r = 0; r < 4; r++) sf[mt][nt][r] = 0.0f;

#pragma unroll
            for (int ks = 0; ks < 4; ks++) {
                uint32_t bf[4][2];
#pragma unroll
                for (int p = 0; p < 2; p++) {
                    const uint32_t addr = ksb + (co + p * 16 + lm_row) * FH_LDB
                                        + ks * 32 + lm_koff;
                    ldsm_x4(bf[2 * p][0], bf[2 * p][1],
                            bf[2 * p + 1][0], bf[2 * p + 1][1], addr);
                }
#pragma unroll
                for (int mt = 0; mt < 2; mt++)
#pragma unroll
                    for (int nt = 0; nt < 4; nt++)
                        mma_f16(sf[mt][nt][0], sf[mt][nt][1],
                                sf[mt][nt][2], sf[mt][nt][3],
                                qf[mt][ks][0], qf[mt][ks][1],
                                qf[mt][ks][2], qf[mt][ks][3],
                                bf[nt][0], bf[nt][1]);
            }

            // --- causal mask (diag band only) ---
            if (kv0 + co + 31 > rmin) {
#pragma unroll
                for (int mt = 0; mt < 2; mt++) {
                    const int r0 = rmin + mt * 16 + g, r1 = r0 + 8;
#pragma unroll
                    for (int nt = 0; nt < 4; nt++) {
                        const int c0 = kv0 + co + nt * 8 + 2 * q, c1 = c0 + 1;
                        if (c0 > r0) sf[mt][nt][0] = MASKV;
                        if (c1 > r0) sf[mt][nt][1] = MASKV;
                        if (c0 > r1) sf[mt][nt][2] = MASKV;
                        if (c1 > r1) sf[mt][nt][3] = MASKV;
                    }
                }
            }

            // --- per-warp online softmax over this warp's half ---
            uint32_t pf[2][4][2];
#pragma unroll
            for (int mt = 0; mt < 2; mt++) {
                float mx0 = MASKV, mx1 = MASKV;
#pragma unroll
                for (int nt = 0; nt < 4; nt++) {
                    mx0 = fmaxf(mx0, fmaxf(sf[mt][nt][0], sf[mt][nt][1]));
                    mx1 = fmaxf(mx1, fmaxf(sf[mt][nt][2], sf[mt][nt][3]));
                }
                mx0 = fmaxf(mx0, __shfl_xor_sync(0xffffffffu, mx0, 1));
                mx0 = fmaxf(mx0, __shfl_xor_sync(0xffffffffu, mx0, 2));
                mx1 = fmaxf(mx1, __shfl_xor_sync(0xffffffffu, mx1, 1));
                mx1 = fmaxf(mx1, __shfl_xor_sync(0xffffffffu, mx1, 2));

                const float mn0 = fmaxf(m[mt][0], mx0);
                const float mn1 = fmaxf(m[mt][1], mx1);
                const float al0 = exp2f(m[mt][0] - mn0);
                const float al1 = exp2f(m[mt][1] - mn1);
                m[mt][0] = mn0; m[mt][1] = mn1;

#pragma unroll
                for (int nt = 0; nt < 4; nt++) {
                    pf[mt][nt][0] = ex2_h2(h2u(__floats2half2_rn(
                        sf[mt][nt][0] - mn0, sf[mt][nt][1] - mn0)));
                    pf[mt][nt][1] = ex2_h2(h2u(__floats2half2_rn(
                        sf[mt][nt][2] - mn1, sf[mt][nt][3] - mn1)));
                }
#pragma unroll
                for (int nt = 0; nt < 8; nt++) {
                    acc[mt][nt][0] *= al0; acc[mt][nt][1] *= al0;
                    acc[mt][nt][2] *= al1; acc[mt][nt][3] *= al1;
                }
                lacc[mt][0] *= al0; lacc[mt][1] *= al0;
                lacc[mt][2] *= al1; lacc[mt][3] *= al1;
            }

            // --- O += P @ V ; l += P @ ones (kv-half, 2 k16 chunks) ---
#pragma unroll
            for (int ks = 0; ks < 2; ks++) {
                uint32_t bf[8][2];
#pragma unroll
                for (int p = 0; p < 4; p++) {
                    const uint32_t addr = vsb + (p * 16 + lm_row) * FH_LDB
                                        + co * 2 + ks * 32 + lm_koff;
                    ldsm_x4(bf[2 * p][0], bf[2 * p][1],
                            bf[2 * p + 1][0], bf[2 * p + 1][1], addr);
                }
#pragma unroll
                for (int mt = 0; mt < 2; mt++) {
                    const uint32_t a0 = pf[mt][2 * ks][0];
                    const uint32_t a1 = pf[mt][2 * ks][1];
                    const uint32_t a2 = pf[mt][2 * ks + 1][0];
                    const uint32_t a3 = pf[mt][2 * ks + 1][1];
#pragma unroll
                    for (int nt = 0; nt < 8; nt++)
                        mma_f16(acc[mt][nt][0], acc[mt][nt][1],
                                acc[mt][nt][2], acc[mt][nt][3],
                                a0, a1, a2, a3, bf[nt][0], bf[nt][1]);
                    mma_f16(lacc[mt][0], lacc[mt][1], lacc[mt][2], lacc[mt][3],
                            a0, a1, a2, a3, ONES_H2, ONES_H2);
                }
            }
        }

        CP_WAIT0();        // next tile's data landed
        __syncthreads();   // stage reuse barrier (1 per tile)
    }

    // --- pair reduction with max reconciliation (reuses smem after barrier) ---
    float* red = (float*)sh;   // 2 groups x 32 lanes x 72 floats = 18432 B
    float* mine = red + (rg * 32 + lane) * 72;
    if (kvh) {
#pragma unroll
        for (int mt = 0; mt < 2; mt++) {
#pragma unroll
            for (int nt = 0; nt < 8; nt++)
                *(float4*)(mine + (mt * 8 + nt) * 4) =
                    make_float4(acc[mt][nt][0], acc[mt][nt][1],
                                acc[mt][nt][2], acc[mt][nt][3]);
            mine[64 + mt * 2 + 0] = lacc[mt][0];
            mine[64 + mt * 2 + 1] = lacc[mt][2];
            mine[68 + mt * 2 + 0] = m[mt][0];
            mine[68 + mt * 2 + 1] = m[mt][1];
        }
    }
    __syncthreads();
    if (!kvh) {
#pragma unroll
        for (int mt = 0; mt < 2; mt++) {
            const float lo0 = mine[64 + mt * 2 + 0];
            const float lo1 = mine[64 + mt * 2 + 1];
            const float mo0 = mine[68 + mt * 2 + 0];
            const float mo1 = mine[68 + mt * 2 + 1];
            const float M0 = fmaxf(m[mt][0], mo0);
            const float M1 = fmaxf(m[mt][1], mo1);
            const float es0 = exp2f(m[mt][0] - M0), eo0 = exp2f(mo0 - M0);
            const float es1 = exp2f(m[mt][1] - M1), eo1 = exp2f(mo1 - M1);
            const float inv0 = 1.0f / (lacc[mt][0] * es0 + lo0 * eo0);
            const float inv1 = 1.0f / (lacc[mt][2] * es1 + lo1 * eo1);
            const int r0 = q0 + rg * 32 + mt * 16 + g;
#pragma unroll
            for (int nt = 0; nt < 8; nt++) {
                float4 t = *(const float4*)(mine + (mt * 8 + nt) * 4);
                const int col = nt * 8 + 2 * q;
                *(__half2*)(O + baseh + (size_t)r0 * DMODEL + col) =
                    __floats2half2_rn((acc[mt][nt][0] * es0 + t.x * eo0) * inv0,
                                      (acc[mt][nt][1] * es0 + t.y * eo0) * inv0);
                *(__half2*)(O + baseh + (size_t)(r0 + 8) * DMODEL + col) =
                    __floats2half2_rn((acc[mt][nt][2] * es1 + t.z * eo1) * inv1,
                                      (acc[mt][nt][3] * es1 + t.w * eo1) * inv1);
            }
        }
    }
}

// ---------------------------------------------------------------------------
// Launch
// ---------------------------------------------------------------------------
extern "C" void kernel_launch(void* const* d_in, const int* in_sizes, int n_in,
                              void* d_out, int out_size)
{
    const float* x  = (const float*)d_in[0];
    const float* Wq = (const float*)d_in[1];
    const float* Wk = (const float*)d_in[2];
    const float* Wv = (const float*)d_in[3];
    const float* Wo = (const float*)d_in[4];
    float* out = (float*)d_out;

    __half *xh, *wh, *qb, *kb, *vb, *ab;
    cudaGetSymbolAddress((void**)&xh, g_xh);
    cudaGetSymbolAddress((void**)&wh, g_wh);
    cudaGetSymbolAddress((void**)&qb, g_q);
    cudaGetSymbolAddress((void**)&kb, g_k);
    cudaGetSymbolAddress((void**)&vb, g_v);
    cudaGetSymbolAddress((void**)&ab, g_a);

    cudaFuncSetAttribute(gemm_qkv,
                         cudaFuncAttributeMaxDynamicSharedMemorySize, GEMM_SMEM);
    cudaFuncSetAttribute(gemm_out,
                         cudaFuncAttributeMaxDynamicSharedMemorySize, GEMM_SMEM);
    cudaFuncSetAttribute(flash_attn_f16,
                         cudaFuncAttributeMaxDynamicSharedMemorySize, FA_SMEM);

    // --- prepass: fp32 -> fp16 for x and all weights ---
    f2h<<<MROWS * DMODEL / 2048, 256>>>(x, xh, MROWS * DMODEL);
    f2h4<<<dim3(DMODEL * DMODEL / 2048, 4), 256>>>(Wq, Wk, Wv, Wo, wh);

    // softmax scale folds 1/sqrt(dk) and log2(e) (flash runs in exp2 domain)
    const float qscale = 0.125f * 1.4426950408889634f;

    // --- fused QKV projections (grid.z = 3) ---
    gemm_qkv<<<dim3(DMODEL / 128, MROWS / 128, 3), 256, GEMM_SMEM>>>(
        xh, wh, qb, kb, vb, qscale);

    flash_attn_f16<<<dim3(SEQ / 64, NHEAD, BSZ), 128, FA_SMEM>>>(qb, kb, vb, ab);

    gemm_out<<<dim3(DMODEL / 128, MROWS / 128), 256, GEMM_SMEM>>>(
        ab, wh + (size_t)3 * DMODEL * DMODEL, out);
}